// round 1
// baseline (speedup 1.0000x reference)
#include <cuda_runtime.h>
#include <math.h>
#include <stdint.h>

#define Bb 64
#define Tt 512
#define Hh 768
#define Nn 2048
#define Pp 300
#define BT (Bb*Tt)

// ---------------- scratch (device globals; no allocation allowed) ----------
__device__ float g_h[(size_t)BT*Hh];        // relu(x@W1^T+b1)
__device__ float g_pooled[(size_t)BT*Hh];   // pooled segments (compacted)
__device__ float g_pm[(size_t)BT*Pp];       // pooled @ Wm^T
__device__ float g_pdT[(size_t)Pp*Nn];      // (ent @ Wd^T)^T  -> [P][N]
__device__ int   g_pred[BT];
__device__ int   g_rowinfo[BT];             // packed (start<<16)|end per valid segment
__device__ int   g_nvraw[Bb];
__device__ int   g_dest[Bb];
__device__ int   g_nvout[Bb];
__device__ int   g_rowvalid[Bb];

// ---------------- generic tiled GEMM: C[M,N] = A[M,K] @ B[N,K]^T ------------
enum { EPI_PLAIN=0, EPI_BIAS_RELU=1, EPI_TRANS=2, EPI_MASK=3 };

template<int EPI>
__global__ void __launch_bounds__(256) gemm_abt(
    const float* __restrict__ A, const float* __restrict__ Bm,
    float* __restrict__ C, int M, int N, int K, int ldc,
    const float* __restrict__ bias, const int* __restrict__ nvalid)
{
    const int BM=128, BN=64, BK=16;
    __shared__ float As[BK][BM];
    __shared__ float Bs[BK][BN];
    const int m0 = blockIdx.y*BM, n0 = blockIdx.x*BN;
    const int tid = threadIdx.x;
    const int tx = tid & 15, ty = tid >> 4;

    int nv = 0;
    if (EPI == EPI_MASK) {
        nv = nvalid[m0 / Tt];
        int t0 = m0 % Tt;            // a 128-row tile never crosses a batch (512%128==0)
        if (t0 >= nv) {
            // fully invalid tile: just write zeros (pm must be 0 for these rows)
            for (int idx = tid; idx < BM*BN; idx += 256) {
                int r = idx >> 6, c = idx & 63;
                int col = n0 + c;
                if (col < N) C[(size_t)(m0 + r)*ldc + col] = 0.f;
            }
            return;
        }
    }

    float acc[8][4];
    #pragma unroll
    for (int i=0;i<8;i++)
        #pragma unroll
        for (int j=0;j<4;j++) acc[i][j] = 0.f;

    for (int k0 = 0; k0 < K; k0 += BK) {
        // A tile: 128 rows x 16 k  (512 float4 over 256 threads)
        #pragma unroll
        for (int it = 0; it < 2; it++) {
            int id = tid + it*256;
            int row = id >> 2, q = id & 3;
            const float4 v = *(const float4*)(A + (size_t)(m0+row)*K + k0 + q*4);
            As[q*4+0][row]=v.x; As[q*4+1][row]=v.y; As[q*4+2][row]=v.z; As[q*4+3][row]=v.w;
        }
        // B tile: 64 rows x 16 k   (256 float4 over 256 threads), guard N edge
        {
            int row = tid >> 2, q = tid & 3;
            float4 v = make_float4(0.f,0.f,0.f,0.f);
            if (n0 + row < N)
                v = *(const float4*)(Bm + (size_t)(n0+row)*K + k0 + q*4);
            Bs[q*4+0][row]=v.x; Bs[q*4+1][row]=v.y; Bs[q*4+2][row]=v.z; Bs[q*4+3][row]=v.w;
        }
        __syncthreads();
        #pragma unroll
        for (int k = 0; k < BK; k++) {
            float4 a0 = *(const float4*)&As[k][ty*8];
            float4 a1 = *(const float4*)&As[k][ty*8+4];
            float4 bv = *(const float4*)&Bs[k][tx*4];
            float av[8] = {a0.x,a0.y,a0.z,a0.w,a1.x,a1.y,a1.z,a1.w};
            float bb[4] = {bv.x,bv.y,bv.z,bv.w};
            #pragma unroll
            for (int i=0;i<8;i++)
                #pragma unroll
                for (int j=0;j<4;j++)
                    acc[i][j] += av[i]*bb[j];
        }
        __syncthreads();
    }

    #pragma unroll
    for (int i=0;i<8;i++){
        int row = m0 + ty*8 + i;
        #pragma unroll
        for (int j=0;j<4;j++){
            int col = n0 + tx*4 + j;
            if (col >= N) continue;
            float v = acc[i][j];
            if (EPI==EPI_BIAS_RELU){ v += bias[col]; v = v>0.f? v:0.f; C[(size_t)row*ldc+col]=v; }
            else if (EPI==EPI_TRANS){ C[(size_t)col*ldc + row] = v; }
            else if (EPI==EPI_MASK){ int t = row % Tt; C[(size_t)row*ldc+col] = (t<nv)? v:0.f; }
            else { C[(size_t)row*ldc+col] = v; }
        }
    }
}

// ---------------- 3-class head: logits + log_softmax + argmax ---------------
__global__ void __launch_bounds__(256) logits_kernel(
    const float* __restrict__ h, const float* __restrict__ W2,
    const float* __restrict__ b2, float* __restrict__ out0, int* __restrict__ pred)
{
    __shared__ float w2s[3*Hh];
    int tid = threadIdx.x;
    for (int i = tid; i < 3*Hh; i += 256) w2s[i] = W2[i];
    __syncthreads();
    int warp = tid >> 5, lane = tid & 31;
    int row = blockIdx.x*8 + warp;
    const float* hp = h + (size_t)row*Hh;
    float s0=0.f, s1=0.f, s2=0.f;
    for (int i = lane; i < Hh; i += 32){
        float hv = hp[i];
        s0 += hv*w2s[i]; s1 += hv*w2s[Hh+i]; s2 += hv*w2s[2*Hh+i];
    }
    #pragma unroll
    for (int off=16; off; off>>=1){
        s0 += __shfl_xor_sync(0xffffffffu, s0, off);
        s1 += __shfl_xor_sync(0xffffffffu, s1, off);
        s2 += __shfl_xor_sync(0xffffffffu, s2, off);
    }
    if (lane == 0){
        s0 += b2[0]; s1 += b2[1]; s2 += b2[2];
        float m = fmaxf(s0, fmaxf(s1, s2));
        float lse = m + logf(expf(s0-m)+expf(s1-m)+expf(s2-m));
        size_t o = (size_t)row*3;
        out0[o+0] = s0 - lse; out0[o+1] = s1 - lse; out0[o+2] = s2 - lse;
        int idx = 0; float best = s0;               // ties -> lowest index (jnp.argmax)
        if (s1 > best){ best = s1; idx = 1; }
        if (s2 > best){ idx = 2; }
        pred[row] = idx;
    }
}

// ---------------- per-batch BIO segment scan (serial, cheap) ----------------
__global__ void scan_kernel(const int* __restrict__ labels,
                            int* __restrict__ rowinfo, int* __restrict__ nvraw,
                            int* __restrict__ rowvalid)
{
    int b = blockIdx.x;
    if (threadIdx.x != 0) return;
    const int* lab = labels + b*Tt;
    int nseg = 0, curstart = 0, hasKept = 0;
    for (int t = 0; t < Tt; t++){
        int l = lab[t];
        if (l == 1){
            if (hasKept) rowinfo[b*Tt + nseg++] = (curstart<<16) | t;
            curstart = t; hasKept = 1;          // the '1' token itself is kept
        } else if (l != 0) hasKept = 1;         // '2' (I-token) is kept
    }
    if (hasKept && nseg < Tt) rowinfo[b*Tt + nseg++] = (curstart<<16) | Tt;
    nvraw[b] = nseg;
    rowvalid[b] = (nseg > 0);
}

__global__ void combine_kernel(const int* __restrict__ nvraw, const int* __restrict__ rowvalid,
                               int* __restrict__ dest, int* __restrict__ nvout)
{
    if (threadIdx.x || blockIdx.x) return;
    int cnt = 0;
    for (int b=0;b<Bb;b++) dest[b] = rowvalid[b] ? cnt++ : -1;
    for (int b=0;b<Bb;b++) nvout[b] = 0;
    for (int b=0;b<Bb;b++) if (dest[b] >= 0) nvout[dest[b]] = nvraw[b];
}

// ---------------- segment means -> compacted pooled rows --------------------
__global__ void __launch_bounds__(256) pool_kernel(
    const int* __restrict__ labels, const float* __restrict__ hidden,
    const int* __restrict__ rowinfo, const int* __restrict__ nvraw,
    const int* __restrict__ dest, float* __restrict__ pooled)
{
    int b = blockIdx.x;
    int d = dest[b];
    if (d < 0) return;
    int nv = nvraw[b];
    __shared__ int labs[Tt];
    int tid = threadIdx.x;
    for (int i=tid;i<Tt;i+=256) labs[i] = labels[b*Tt+i];
    __syncthreads();
    int r0 = blockIdx.y * 32;
    int r1 = min(r0+32, nv);
    for (int r=r0; r<r1; r++){
        int info = rowinfo[b*Tt + r];
        int s = info >> 16, e = info & 0xffff;
        float a0=0.f,a1=0.f,a2=0.f;
        int cnt = 0;
        for (int t=s;t<e;t++){
            if (labs[t] != 0){
                cnt++;
                const float* hp = hidden + ((size_t)(b*Tt)+t)*Hh;
                a0 += hp[tid]; a1 += hp[tid+256]; a2 += hp[tid+512];
            }
        }
        float inv = 1.0f / (float)cnt;               // cnt >= 1 for valid segments
        float* op = pooled + ((size_t)(d*Tt)+r)*Hh;
        op[tid] = a0*inv; op[tid+256] = a1*inv; op[tid+512] = a2*inv;
    }
}

// ---------------- fused score GEMM (pm @ pd^T) + log_softmax ----------------
__global__ void __launch_bounds__(256) score_kernel(
    const float* __restrict__ pm, const float* __restrict__ pdT,
    const int* __restrict__ nvalid, float* __restrict__ out)
{
    extern __shared__ float sh[];
    float* sc  = sh;             // 8 * 2048 scores
    float* pms = sh + 8*Nn;      // 8 * 304 (padded pm rows, float4 aligned)
    const int tid = threadIdx.x;
    const int b  = blockIdx.y;
    const int t0 = blockIdx.x * 8;
    const int nv = nvalid[b];

    if (t0 >= nv){
        // all-zero pooled rows -> log_softmax(0) = -log(2048) everywhere
        const float CNEG = -7.6246189861593985f;
        #pragma unroll
        for (int r=0;r<8;r++){
            float* op = out + ((size_t)(b*Tt + t0 + r))*Nn;
            for (int i=tid;i<Nn;i+=256) op[i] = CNEG;
        }
        return;
    }

    #pragma unroll
    for (int r=0;r<8;r++){
        const float* ip = pm + ((size_t)(b*Tt + t0 + r))*Pp;
        for (int i=tid;i<Pp;i+=256) pms[r*304+i] = ip[i];
    }
    __syncthreads();

    #pragma unroll 1
    for (int chunk=0; chunk<8; chunk++){
        int n = chunk*256 + tid;
        float acc[8];
        #pragma unroll
        for (int r=0;r<8;r++) acc[r]=0.f;
        const float* pp = pdT + n;
        for (int k4=0;k4<75;k4++){                  // K = 300 = 75*4 exactly
            float p0 = pp[(4*k4+0)*Nn];
            float p1 = pp[(4*k4+1)*Nn];
            float p2 = pp[(4*k4+2)*Nn];
            float p3 = pp[(4*k4+3)*Nn];
            #pragma unroll
            for (int r=0;r<8;r++){
                float4 v = *(const float4*)&pms[r*304 + 4*k4];
                acc[r] += v.x*p0 + v.y*p1 + v.z*p2 + v.w*p3;
            }
        }
        #pragma unroll
        for (int r=0;r<8;r++) sc[r*Nn + n] = acc[r];
    }
    __syncthreads();

    // warp w handles row w: max / logsumexp / write
    int r = tid >> 5, lane = tid & 31;
    const float* row = sc + r*Nn;
    float m = -3.4e38f;
    for (int i=lane;i<Nn;i+=32) m = fmaxf(m, row[i]);
    #pragma unroll
    for (int off=16;off;off>>=1) m = fmaxf(m, __shfl_xor_sync(0xffffffffu, m, off));
    float s = 0.f;
    for (int i=lane;i<Nn;i+=32) s += expf(row[i]-m);
    #pragma unroll
    for (int off=16;off;off>>=1) s += __shfl_xor_sync(0xffffffffu, s, off);
    float corr = m + logf(s);
    float* op = out + ((size_t)(b*Tt + t0 + r))*Nn;
    for (int i=lane;i<Nn;i+=32) op[i] = row[i] - corr;
}

// ---------------- host ------------------------------------------------------
extern "C" void kernel_launch(void* const* d_in, const int* in_sizes, int n_in,
                              void* d_out, int out_size)
{
    (void)in_sizes; (void)n_in; (void)out_size;
    const int*   labels = (const int*)  d_in[0];
    const float* hidden = (const float*)d_in[1];
    const float* ent    = (const float*)d_in[2];
    const float* W1     = (const float*)d_in[3];
    const float* b1     = (const float*)d_in[4];
    const float* W2     = (const float*)d_in[5];
    const float* b2     = (const float*)d_in[6];
    const float* Wm     = (const float*)d_in[7];
    const float* Wd     = (const float*)d_in[8];

    float* out0 = (float*)d_out;
    float* s1o  = out0 + (size_t)BT*3;
    float* s2o  = s1o  + (size_t)BT*Nn;

    float *h, *pooled, *pm, *pdT;
    int *pred, *rowinfo, *nvraw, *dest, *nvout, *rowvalid;
    cudaGetSymbolAddress((void**)&h,       g_h);
    cudaGetSymbolAddress((void**)&pooled,  g_pooled);
    cudaGetSymbolAddress((void**)&pm,      g_pm);
    cudaGetSymbolAddress((void**)&pdT,     g_pdT);
    cudaGetSymbolAddress((void**)&pred,    g_pred);
    cudaGetSymbolAddress((void**)&rowinfo, g_rowinfo);
    cudaGetSymbolAddress((void**)&nvraw,   g_nvraw);
    cudaGetSymbolAddress((void**)&dest,    g_dest);
    cudaGetSymbolAddress((void**)&nvout,   g_nvout);
    cudaGetSymbolAddress((void**)&rowvalid,g_rowvalid);

    const size_t SHM = (size_t)(8*Nn + 8*304)*sizeof(float);   // 75264 B
    cudaFuncSetAttribute(score_kernel, cudaFuncAttributeMaxDynamicSharedMemorySize, (int)SHM);

    // 1) h = relu(x @ W1^T + b1)
    gemm_abt<EPI_BIAS_RELU><<<dim3(Hh/64, BT/128), 256>>>(
        hidden, W1, h, BT, Hh, Hh, Hh, b1, nullptr);

    // 2) bio logits -> out0 + predicted labels
    logits_kernel<<<BT/8, 256>>>(h, W2, b2, out0, pred);

    // 3) pdT[p][n] = (ent @ Wd^T)[n][p]
    gemm_abt<EPI_TRANS><<<dim3((Pp+63)/64, Nn/128), 256>>>(
        ent, Wd, pdT, Nn, Pp, Hh, Nn, nullptr, nullptr);

    // 4/5) two pooling passes: gold labels, then predicted
    for (int pass = 0; pass < 2; pass++){
        const int* lsrc = (pass == 0) ? labels : pred;
        float* so = (pass == 0) ? s1o : s2o;

        scan_kernel<<<Bb, 32>>>(lsrc, rowinfo, nvraw, rowvalid);
        combine_kernel<<<1, 1>>>(nvraw, rowvalid, dest, nvout);
        pool_kernel<<<dim3(Bb, 16), 256>>>(lsrc, hidden, rowinfo, nvraw, dest, pooled);
        gemm_abt<EPI_MASK><<<dim3((Pp+63)/64, BT/128), 256>>>(
            pooled, Wm, pm, BT, Pp, Hh, Pp, nullptr, nvout);
        score_kernel<<<dim3(Tt/8, Bb), 256, SHM>>>(pm, pdT, nvout, so);
    }
}

// round 2
// speedup vs baseline: 1.0064x; 1.0064x over previous
#include <cuda_runtime.h>
#include <math.h>
#include <stdint.h>

#define Bb 64
#define Tt 512
#define Hh 768
#define Nn 2048
#define Pp 300
#define BT (Bb*Tt)

// ---------------- scratch (device globals; no allocation allowed) ----------
__device__ float g_h[(size_t)BT*Hh];        // relu(x@W1^T+b1)
__device__ float g_pooled[(size_t)BT*Hh];   // pooled segments (compacted)
__device__ float g_pm[(size_t)BT*Pp];       // pooled @ Wm^T
__device__ float g_pdT[(size_t)Pp*Nn];      // (ent @ Wd^T)^T  -> [P][N]
__device__ int   g_pred[BT];
__device__ int   g_rowinfo[BT];             // packed (start<<16)|end per valid segment
__device__ int   g_nvraw[Bb];
__device__ int   g_dest[Bb];
__device__ int   g_nvout[Bb];
__device__ int   g_rowvalid[Bb];

// ---------------- generic tiled GEMM: C[M,N] = A[M,K] @ B[N,K]^T ------------
enum { EPI_PLAIN=0, EPI_BIAS_RELU=1, EPI_TRANS=2, EPI_MASK=3 };

template<int EPI>
__global__ void __launch_bounds__(256) gemm_abt(
    const float* __restrict__ A, const float* __restrict__ Bm,
    float* __restrict__ C, int M, int N, int K, int ldc,
    const float* __restrict__ bias, const int* __restrict__ nvalid)
{
    const int BM=128, BN=64, BK=16;
    __shared__ float As[BK][BM];
    __shared__ float Bs[BK][BN];
    const int m0 = blockIdx.y*BM, n0 = blockIdx.x*BN;
    const int tid = threadIdx.x;
    const int tx = tid & 15, ty = tid >> 4;

    int nv = 0;
    if (EPI == EPI_MASK) {
        nv = nvalid[m0 / Tt];
        int t0 = m0 % Tt;            // a 128-row tile never crosses a batch (512%128==0)
        if (t0 >= nv) {
            // fully invalid tile: just write zeros (pm must be 0 for these rows)
            for (int idx = tid; idx < BM*BN; idx += 256) {
                int r = idx >> 6, c = idx & 63;
                int col = n0 + c;
                if (col < N) C[(size_t)(m0 + r)*ldc + col] = 0.f;
            }
            return;
        }
    }

    float acc[8][4];
    #pragma unroll
    for (int i=0;i<8;i++)
        #pragma unroll
        for (int j=0;j<4;j++) acc[i][j] = 0.f;

    for (int k0 = 0; k0 < K; k0 += BK) {
        // A tile: 128 rows x 16 k  (512 float4 over 256 threads)
        #pragma unroll
        for (int it = 0; it < 2; it++) {
            int id = tid + it*256;
            int row = id >> 2, q = id & 3;
            const float4 v = *(const float4*)(A + (size_t)(m0+row)*K + k0 + q*4);
            As[q*4+0][row]=v.x; As[q*4+1][row]=v.y; As[q*4+2][row]=v.z; As[q*4+3][row]=v.w;
        }
        // B tile: 64 rows x 16 k   (256 float4 over 256 threads), guard N edge
        {
            int row = tid >> 2, q = tid & 3;
            float4 v = make_float4(0.f,0.f,0.f,0.f);
            if (n0 + row < N)
                v = *(const float4*)(Bm + (size_t)(n0+row)*K + k0 + q*4);
            Bs[q*4+0][row]=v.x; Bs[q*4+1][row]=v.y; Bs[q*4+2][row]=v.z; Bs[q*4+3][row]=v.w;
        }
        __syncthreads();
        #pragma unroll
        for (int k = 0; k < BK; k++) {
            float4 a0 = *(const float4*)&As[k][ty*8];
            float4 a1 = *(const float4*)&As[k][ty*8+4];
            float4 bv = *(const float4*)&Bs[k][tx*4];
            float av[8] = {a0.x,a0.y,a0.z,a0.w,a1.x,a1.y,a1.z,a1.w};
            float bb[4] = {bv.x,bv.y,bv.z,bv.w};
            #pragma unroll
            for (int i=0;i<8;i++)
                #pragma unroll
                for (int j=0;j<4;j++)
                    acc[i][j] += av[i]*bb[j];
        }
        __syncthreads();
    }

    #pragma unroll
    for (int i=0;i<8;i++){
        int row = m0 + ty*8 + i;
        #pragma unroll
        for (int j=0;j<4;j++){
            int col = n0 + tx*4 + j;
            if (col >= N) continue;
            float v = acc[i][j];
            if (EPI==EPI_BIAS_RELU){ v += bias[col]; v = v>0.f? v:0.f; C[(size_t)row*ldc+col]=v; }
            else if (EPI==EPI_TRANS){ C[(size_t)col*ldc + row] = v; }
            else if (EPI==EPI_MASK){ int t = row % Tt; C[(size_t)row*ldc+col] = (t<nv)? v:0.f; }
            else { C[(size_t)row*ldc+col] = v; }
        }
    }
}

// ---------------- 3-class head: logits + log_softmax + argmax ---------------
__global__ void __launch_bounds__(256) logits_kernel(
    const float* __restrict__ h, const float* __restrict__ W2,
    const float* __restrict__ b2, float* __restrict__ out0, int* __restrict__ pred)
{
    __shared__ float w2s[3*Hh];
    int tid = threadIdx.x;
    for (int i = tid; i < 3*Hh; i += 256) w2s[i] = W2[i];
    __syncthreads();
    int warp = tid >> 5, lane = tid & 31;
    int row = blockIdx.x*8 + warp;
    const float* hp = h + (size_t)row*Hh;
    float s0=0.f, s1=0.f, s2=0.f;
    for (int i = lane; i < Hh; i += 32){
        float hv = hp[i];
        s0 += hv*w2s[i]; s1 += hv*w2s[Hh+i]; s2 += hv*w2s[2*Hh+i];
    }
    #pragma unroll
    for (int off=16; off; off>>=1){
        s0 += __shfl_xor_sync(0xffffffffu, s0, off);
        s1 += __shfl_xor_sync(0xffffffffu, s1, off);
        s2 += __shfl_xor_sync(0xffffffffu, s2, off);
    }
    if (lane == 0){
        s0 += b2[0]; s1 += b2[1]; s2 += b2[2];
        float m = fmaxf(s0, fmaxf(s1, s2));
        float lse = m + logf(expf(s0-m)+expf(s1-m)+expf(s2-m));
        size_t o = (size_t)row*3;
        out0[o+0] = s0 - lse; out0[o+1] = s1 - lse; out0[o+2] = s2 - lse;
        int idx = 0; float best = s0;               // ties -> lowest index (jnp.argmax)
        if (s1 > best){ best = s1; idx = 1; }
        if (s2 > best){ idx = 2; }
        pred[row] = idx;
    }
}

// ---------------- per-batch BIO segment scan (serial, cheap) ----------------
__global__ void scan_kernel(const int* __restrict__ labels,
                            int* __restrict__ rowinfo, int* __restrict__ nvraw,
                            int* __restrict__ rowvalid)
{
    int b = blockIdx.x;
    if (threadIdx.x != 0) return;
    const int* lab = labels + b*Tt;
    int nseg = 0, curstart = 0, hasKept = 0;
    for (int t = 0; t < Tt; t++){
        int l = lab[t];
        if (l == 1){
            if (hasKept) rowinfo[b*Tt + nseg++] = (curstart<<16) | t;
            curstart = t; hasKept = 1;          // the '1' token itself is kept
        } else if (l != 0) hasKept = 1;         // '2' (I-token) is kept
    }
    if (hasKept && nseg < Tt) rowinfo[b*Tt + nseg++] = (curstart<<16) | Tt;
    nvraw[b] = nseg;
    rowvalid[b] = (nseg > 0);
}

__global__ void combine_kernel(const int* __restrict__ nvraw, const int* __restrict__ rowvalid,
                               int* __restrict__ dest, int* __restrict__ nvout)
{
    if (threadIdx.x || blockIdx.x) return;
    int cnt = 0;
    for (int b=0;b<Bb;b++) dest[b] = rowvalid[b] ? cnt++ : -1;
    for (int b=0;b<Bb;b++) nvout[b] = 0;
    for (int b=0;b<Bb;b++) if (dest[b] >= 0) nvout[dest[b]] = nvraw[b];
}

// ---------------- segment means -> compacted pooled rows --------------------
__global__ void __launch_bounds__(256) pool_kernel(
    const int* __restrict__ labels, const float* __restrict__ hidden,
    const int* __restrict__ rowinfo, const int* __restrict__ nvraw,
    const int* __restrict__ dest, float* __restrict__ pooled)
{
    int b = blockIdx.x;
    int d = dest[b];
    if (d < 0) return;
    int nv = nvraw[b];
    __shared__ int labs[Tt];
    int tid = threadIdx.x;
    for (int i=tid;i<Tt;i+=256) labs[i] = labels[b*Tt+i];
    __syncthreads();
    int r0 = blockIdx.y * 32;
    int r1 = min(r0+32, nv);
    for (int r=r0; r<r1; r++){
        int info = rowinfo[b*Tt + r];
        int s = info >> 16, e = info & 0xffff;
        float a0=0.f,a1=0.f,a2=0.f;
        int cnt = 0;
        for (int t=s;t<e;t++){
            if (labs[t] != 0){
                cnt++;
                const float* hp = hidden + ((size_t)(b*Tt)+t)*Hh;
                a0 += hp[tid]; a1 += hp[tid+256]; a2 += hp[tid+512];
            }
        }
        float inv = 1.0f / (float)cnt;               // cnt >= 1 for valid segments
        float* op = pooled + ((size_t)(d*Tt)+r)*Hh;
        op[tid] = a0*inv; op[tid+256] = a1*inv; op[tid+512] = a2*inv;
    }
}

// ---------------- fused score GEMM (pm @ pd^T) + log_softmax ----------------
__global__ void __launch_bounds__(256) score_kernel(
    const float* __restrict__ pm, const float* __restrict__ pdT,
    const int* __restrict__ nvalid, float* __restrict__ out)
{
    extern __shared__ float sh[];
    float* sc  = sh;             // 8 * 2048 scores
    float* pms = sh + 8*Nn;      // 8 * 304 (padded pm rows, float4 aligned)
    const int tid = threadIdx.x;
    const int b  = blockIdx.y;
    const int t0 = blockIdx.x * 8;
    const int nv = nvalid[b];

    if (t0 >= nv){
        // all-zero pooled rows -> log_softmax(0) = -log(2048) everywhere
        const float CNEG = -7.6246189861593985f;
        #pragma unroll
        for (int r=0;r<8;r++){
            float* op = out + ((size_t)(b*Tt + t0 + r))*Nn;
            for (int i=tid;i<Nn;i+=256) op[i] = CNEG;
        }
        return;
    }

    #pragma unroll
    for (int r=0;r<8;r++){
        const float* ip = pm + ((size_t)(b*Tt + t0 + r))*Pp;
        for (int i=tid;i<Pp;i+=256) pms[r*304+i] = ip[i];
    }
    __syncthreads();

    #pragma unroll 1
    for (int chunk=0; chunk<8; chunk++){
        int n = chunk*256 + tid;
        float acc[8];
        #pragma unroll
        for (int r=0;r<8;r++) acc[r]=0.f;
        const float* pp = pdT + n;
        for (int k4=0;k4<75;k4++){                  // K = 300 = 75*4 exactly
            float p0 = pp[(4*k4+0)*Nn];
            float p1 = pp[(4*k4+1)*Nn];
            float p2 = pp[(4*k4+2)*Nn];
            float p3 = pp[(4*k4+3)*Nn];
            #pragma unroll
            for (int r=0;r<8;r++){
                float4 v = *(const float4*)&pms[r*304 + 4*k4];
                acc[r] += v.x*p0 + v.y*p1 + v.z*p2 + v.w*p3;
            }
        }
        #pragma unroll
        for (int r=0;r<8;r++) sc[r*Nn + n] = acc[r];
    }
    __syncthreads();

    // warp w handles row w: max / logsumexp / write
    int r = tid >> 5, lane = tid & 31;
    const float* row = sc + r*Nn;
    float m = -3.4e38f;
    for (int i=lane;i<Nn;i+=32) m = fmaxf(m, row[i]);
    #pragma unroll
    for (int off=16;off;off>>=1) m = fmaxf(m, __shfl_xor_sync(0xffffffffu, m, off));
    float s = 0.f;
    for (int i=lane;i<Nn;i+=32) s += expf(row[i]-m);
    #pragma unroll
    for (int off=16;off;off>>=1) s += __shfl_xor_sync(0xffffffffu, s, off);
    float corr = m + logf(s);
    float* op = out + ((size_t)(b*Tt + t0 + r))*Nn;
    for (int i=lane;i<Nn;i+=32) op[i] = row[i] - corr;
}

// ---------------- host ------------------------------------------------------
extern "C" void kernel_launch(void* const* d_in, const int* in_sizes, int n_in,
                              void* d_out, int out_size)
{
    (void)in_sizes; (void)n_in; (void)out_size;
    const int*   labels = (const int*)  d_in[0];
    const float* hidden = (const float*)d_in[1];
    const float* ent    = (const float*)d_in[2];
    const float* W1     = (const float*)d_in[3];
    const float* b1     = (const float*)d_in[4];
    const float* W2     = (const float*)d_in[5];
    const float* b2     = (const float*)d_in[6];
    const float* Wm     = (const float*)d_in[7];
    const float* Wd     = (const float*)d_in[8];

    float* out0 = (float*)d_out;
    float* s1o  = out0 + (size_t)BT*3;
    float* s2o  = s1o  + (size_t)BT*Nn;

    float *h, *pooled, *pm, *pdT;
    int *pred, *rowinfo, *nvraw, *dest, *nvout, *rowvalid;
    cudaGetSymbolAddress((void**)&h,       g_h);
    cudaGetSymbolAddress((void**)&pooled,  g_pooled);
    cudaGetSymbolAddress((void**)&pm,      g_pm);
    cudaGetSymbolAddress((void**)&pdT,     g_pdT);
    cudaGetSymbolAddress((void**)&pred,    g_pred);
    cudaGetSymbolAddress((void**)&rowinfo, g_rowinfo);
    cudaGetSymbolAddress((void**)&nvraw,   g_nvraw);
    cudaGetSymbolAddress((void**)&dest,    g_dest);
    cudaGetSymbolAddress((void**)&nvout,   g_nvout);
    cudaGetSymbolAddress((void**)&rowvalid,g_rowvalid);

    const size_t SHM = (size_t)(8*Nn + 8*304)*sizeof(float);   // 75264 B
    cudaFuncSetAttribute(score_kernel, cudaFuncAttributeMaxDynamicSharedMemorySize, (int)SHM);

    // 1) h = relu(x @ W1^T + b1)
    gemm_abt<EPI_BIAS_RELU><<<dim3(Hh/64, BT/128), 256>>>(
        hidden, W1, h, BT, Hh, Hh, Hh, b1, nullptr);

    // 2) bio logits -> out0 + predicted labels
    logits_kernel<<<BT/8, 256>>>(h, W2, b2, out0, pred);

    // 3) pdT[p][n] = (ent @ Wd^T)[n][p]
    gemm_abt<EPI_TRANS><<<dim3((Pp+63)/64, Nn/128), 256>>>(
        ent, Wd, pdT, Nn, Pp, Hh, Nn, nullptr, nullptr);

    // 4/5) two pooling passes: gold labels, then predicted
    for (int pass = 0; pass < 2; pass++){
        const int* lsrc = (pass == 0) ? labels : pred;
        float* so = (pass == 0) ? s1o : s2o;

        scan_kernel<<<Bb, 32>>>(lsrc, rowinfo, nvraw, rowvalid);
        combine_kernel<<<1, 1>>>(nvraw, rowvalid, dest, nvout);
        pool_kernel<<<dim3(Bb, 16), 256>>>(lsrc, hidden, rowinfo, nvraw, dest, pooled);
        gemm_abt<EPI_MASK><<<dim3((Pp+63)/64, BT/128), 256>>>(
            pooled, Wm, pm, BT, Pp, Hh, Pp, nullptr, nvout);
        score_kernel<<<dim3(Tt/8, Bb), 256, SHM>>>(pm, pdT, nvout, so);
    }
}

// round 4
// speedup vs baseline: 1.5423x; 1.5325x over previous
#include <cuda_runtime.h>
#include <math.h>
#include <stdint.h>

#define Bb 64
#define Tt 512
#define Hh 768
#define Nn 2048
#define Pp 300
#define KP 320
#define BT (Bb*Tt)

// ---------------- scratch (device globals; no allocation allowed) ----------
__device__ float g_h[(size_t)BT*Hh];
__device__ float g_pooled[(size_t)BT*Hh];
__device__ float g_pm[(size_t)BT*KP];
__device__ float g_pd[(size_t)Nn*KP];
__device__ float g_sc[(size_t)BT*Nn];
__device__ int   g_pred[BT];
__device__ int   g_rowinfo[BT];
__device__ int   g_nvraw[Bb];
__device__ int   g_dest[Bb];
__device__ int   g_nvout[Bb];
__device__ int   g_rowvalid[Bb];

// ---------------- helpers ----------------------------------------------------
__device__ __forceinline__ uint32_t smem_u32(const void* p){
    uint32_t a;
    asm("{ .reg .u64 t; cvta.to.shared.u64 t, %1; cvt.u32.u64 %0, t; }" : "=r"(a) : "l"(p));
    return a;
}
__device__ __forceinline__ void cp_async16(uint32_t dst, const float* src, bool ok){
    int sz = ok ? 16 : 0;   // src-size 0 -> zero-fill 16B
    asm volatile("cp.async.cg.shared.global [%0], [%1], 16, %2;" :: "r"(dst), "l"(src), "r"(sz));
}
__device__ __forceinline__ void cp_commit(){ asm volatile("cp.async.commit_group;" ::: "memory"); }
template<int N> __device__ __forceinline__ void cp_wait(){ asm volatile("cp.async.wait_group %0;" :: "n"(N) : "memory"); }

// split x into tf32-exact hi (top 10 mantissa bits) + tf32-rounded lo
__device__ __forceinline__ void split2(float x, uint32_t& hi, uint32_t& lo){
    uint32_t h = __float_as_uint(x) & 0xFFFFE000u;
    hi = h;
    float l = x - __uint_as_float(h);
    uint32_t lr;
    asm("cvt.rna.tf32.f32 %0, %1;" : "=r"(lr) : "f"(l));
    lo = lr;
}
__device__ __forceinline__ void mma8(float* d, const uint32_t* a, const uint32_t* b){
    asm volatile(
        "mma.sync.aligned.m16n8k8.row.col.f32.tf32.tf32.f32 "
        "{%0,%1,%2,%3}, {%4,%5,%6,%7}, {%8,%9}, {%0,%1,%2,%3};"
        : "+f"(d[0]), "+f"(d[1]), "+f"(d[2]), "+f"(d[3])
        : "r"(a[0]), "r"(a[1]), "r"(a[2]), "r"(a[3]), "r"(b[0]), "r"(b[1]));
}

// ---------------- tensor-core 3xTF32 GEMM: C[M,N] = A[M,K] @ B[N,K]^T -------
enum { EP_BIASRELU = 0, EP_PAD = 1, EP_PLAIN = 2 };
#define SLD 36
#define TILEF (128*SLD)
#define SMEMSZ (4*TILEF*4)

template<int EPI, bool ROWMASK>
__global__ void __launch_bounds__(256, 1) mma_gemm(
    const float* __restrict__ A, const float* __restrict__ Bm,
    float* __restrict__ C, int lda, int ldb, int ldc,
    int K, int Nreal, int NBreal,
    const float* __restrict__ bias, const int* __restrict__ nvout)
{
    extern __shared__ float sm[];
    const int m0 = blockIdx.y * 128, n0 = blockIdx.x * 128;
    const int tid = threadIdx.x;
    if (ROWMASK){
        int nv = nvout[m0 >> 9];        // 128-row tile never crosses a batch
        if ((m0 & 511) >= nv) return;   // outputs for invalid rows are never read
    }
    float* Asm[2] = { sm,           sm + TILEF };
    float* Bsm[2] = { sm + 2*TILEF, sm + 3*TILEF };

    const int warp = tid >> 5, lane = tid & 31;
    const int wm = warp & 1, wn = warp >> 1;     // 2 x 4 warp grid
    const int lr = lane >> 2, lc = lane & 3;

    float acc[4][4][4];
    #pragma unroll
    for (int i=0;i<4;i++)
        #pragma unroll
        for (int j=0;j<4;j++)
            #pragma unroll
            for (int q=0;q<4;q++) acc[i][j][q] = 0.f;

    auto load_tile = [&](int kt, int s){
        const int k0 = kt * 32;
        const uint32_t ab = smem_u32(Asm[s]);
        const uint32_t bb = smem_u32(Bsm[s]);
        #pragma unroll
        for (int j = 0; j < 4; j++){
            int idx = tid + j*256;
            int row = idx >> 3, q = idx & 7;
            uint32_t so = (uint32_t)(row*SLD + q*4) * 4u;
            cp_async16(ab + so, A + (size_t)(m0 + row)*lda + k0 + q*4, true);
            bool ok = (n0 + row) < NBreal;
            const float* bs = ok ? (Bm + (size_t)(n0 + row)*ldb + k0 + q*4) : Bm;
            cp_async16(bb + so, bs, ok);
        }
        cp_commit();
    };

    const int nkt = K >> 5;
    load_tile(0, 0);
    for (int kt = 0; kt < nkt; kt++){
        const int s = kt & 1;
        if (kt + 1 < nkt){ load_tile(kt + 1, s ^ 1); cp_wait<1>(); }
        else cp_wait<0>();
        __syncthreads();
        const float* as = Asm[s];
        const float* bs = Bsm[s];

        #pragma unroll
        for (int ks = 0; ks < 4; ks++){
            const int kb = ks * 8;
            uint32_t ah[4][4], al[4][4], bh[4][2], bl[4][2];
            #pragma unroll
            for (int mt = 0; mt < 4; mt++){
                int r = wm*64 + mt*16 + lr;
                int c = kb + lc;
                split2(as[r*SLD + c],         ah[mt][0], al[mt][0]);
                split2(as[(r+8)*SLD + c],     ah[mt][1], al[mt][1]);
                split2(as[r*SLD + c + 4],     ah[mt][2], al[mt][2]);
                split2(as[(r+8)*SLD + c + 4], ah[mt][3], al[mt][3]);
            }
            #pragma unroll
            for (int nt = 0; nt < 4; nt++){
                int n = wn*32 + nt*8 + lr;
                int k = kb + lc;
                split2(bs[n*SLD + k],     bh[nt][0], bl[nt][0]);
                split2(bs[n*SLD + k + 4], bh[nt][1], bl[nt][1]);
            }
            #pragma unroll
            for (int mt = 0; mt < 4; mt++)
                #pragma unroll
                for (int nt = 0; nt < 4; nt++){
                    mma8(acc[mt][nt], ah[mt], bh[nt]);
                    mma8(acc[mt][nt], ah[mt], bl[nt]);
                    mma8(acc[mt][nt], al[mt], bh[nt]);
                }
        }
        __syncthreads();
    }

    // epilogue: direct register -> gmem (float2 per fragment half)
    #pragma unroll
    for (int mt = 0; mt < 4; mt++){
        #pragma unroll
        for (int nt = 0; nt < 4; nt++){
            int row = m0 + wm*64 + mt*16 + lr;
            int col = n0 + wn*32 + nt*8 + lc*2;
            float* a = acc[mt][nt];
            if (EPI == EP_BIASRELU){
                float b0 = bias[col], b1 = bias[col+1];
                float v0 = a[0] + b0, v1 = a[1] + b1, v2 = a[2] + b0, v3 = a[3] + b1;
                v0 = v0 > 0.f ? v0 : 0.f; v1 = v1 > 0.f ? v1 : 0.f;
                v2 = v2 > 0.f ? v2 : 0.f; v3 = v3 > 0.f ? v3 : 0.f;
                *(float2*)&C[(size_t)row*ldc + col]     = make_float2(v0, v1);
                *(float2*)&C[(size_t)(row+8)*ldc + col] = make_float2(v2, v3);
            } else if (EPI == EP_PLAIN){
                *(float2*)&C[(size_t)row*ldc + col]     = make_float2(a[0], a[1]);
                *(float2*)&C[(size_t)(row+8)*ldc + col] = make_float2(a[2], a[3]);
            } else { // EP_PAD: zero the K-pad columns, guard ldc edge
                if (col + 1 < ldc){
                    float v0 = (col   < Nreal) ? a[0] : 0.f;
                    float v1 = (col+1 < Nreal) ? a[1] : 0.f;
                    float v2 = (col   < Nreal) ? a[2] : 0.f;
                    float v3 = (col+1 < Nreal) ? a[3] : 0.f;
                    *(float2*)&C[(size_t)row*ldc + col]     = make_float2(v0, v1);
                    *(float2*)&C[(size_t)(row+8)*ldc + col] = make_float2(v2, v3);
                }
            }
        }
    }
}

// ---------------- 3-class head ------------------------------------------------
__global__ void __launch_bounds__(256) logits_kernel(
    const float* __restrict__ h, const float* __restrict__ W2,
    const float* __restrict__ b2, float* __restrict__ out0, int* __restrict__ pred)
{
    __shared__ float w2s[3*Hh];
    int tid = threadIdx.x;
    for (int i = tid; i < 3*Hh; i += 256) w2s[i] = W2[i];
    __syncthreads();
    int warp = tid >> 5, lane = tid & 31;
    int row = blockIdx.x*8 + warp;
    const float* hp = h + (size_t)row*Hh;
    float s0=0.f, s1=0.f, s2=0.f;
    for (int i = lane; i < Hh; i += 32){
        float hv = hp[i];
        s0 += hv*w2s[i]; s1 += hv*w2s[Hh+i]; s2 += hv*w2s[2*Hh+i];
    }
    #pragma unroll
    for (int off=16; off; off>>=1){
        s0 += __shfl_xor_sync(0xffffffffu, s0, off);
        s1 += __shfl_xor_sync(0xffffffffu, s1, off);
        s2 += __shfl_xor_sync(0xffffffffu, s2, off);
    }
    if (lane == 0){
        s0 += b2[0]; s1 += b2[1]; s2 += b2[2];
        float m = fmaxf(s0, fmaxf(s1, s2));
        float lse = m + logf(expf(s0-m)+expf(s1-m)+expf(s2-m));
        size_t o = (size_t)row*3;
        out0[o+0] = s0 - lse; out0[o+1] = s1 - lse; out0[o+2] = s2 - lse;
        int idx = 0; float best = s0;
        if (s1 > best){ best = s1; idx = 1; }
        if (s2 > best){ idx = 2; }
        pred[row] = idx;
    }
}

// ---------------- BIO segment scan --------------------------------------------
__global__ void scan_kernel(const int* __restrict__ labels,
                            int* __restrict__ rowinfo, int* __restrict__ nvraw,
                            int* __restrict__ rowvalid)
{
    __shared__ int labs[Tt];
    int b = blockIdx.x;
    for (int i = threadIdx.x; i < Tt; i += 32) labs[i] = labels[b*Tt + i];
    __syncwarp();
    if (threadIdx.x != 0) return;
    int nseg = 0, curstart = 0, hasKept = 0;
    for (int t = 0; t < Tt; t++){
        int l = labs[t];
        if (l == 1){
            if (hasKept) rowinfo[b*Tt + nseg++] = (curstart<<16) | t;
            curstart = t; hasKept = 1;
        } else if (l != 0) hasKept = 1;
    }
    if (hasKept && nseg < Tt) rowinfo[b*Tt + nseg++] = (curstart<<16) | Tt;
    nvraw[b] = nseg;
    rowvalid[b] = (nseg > 0);
}

__global__ void combine_kernel(const int* __restrict__ nvraw, const int* __restrict__ rowvalid,
                               int* __restrict__ dest, int* __restrict__ nvout)
{
    if (threadIdx.x || blockIdx.x) return;
    int cnt = 0;
    for (int b=0;b<Bb;b++) dest[b] = rowvalid[b] ? cnt++ : -1;
    for (int b=0;b<Bb;b++) nvout[b] = 0;
    for (int b=0;b<Bb;b++) if (dest[b] >= 0) nvout[dest[b]] = nvraw[b];
}

// ---------------- segment means -> compacted pooled rows -----------------------
__global__ void __launch_bounds__(256) pool_kernel(
    const int* __restrict__ labels, const float* __restrict__ hidden,
    const int* __restrict__ rowinfo, const int* __restrict__ nvraw,
    const int* __restrict__ dest, float* __restrict__ pooled)
{
    int b = blockIdx.x;
    int d = dest[b];
    if (d < 0) return;
    int nv = nvraw[b];
    __shared__ int labs[Tt];
    int tid = threadIdx.x;
    for (int i=tid;i<Tt;i+=256) labs[i] = labels[b*Tt+i];
    __syncthreads();
    int r0 = blockIdx.y * 32;
    int r1 = min(r0+32, nv);
    for (int r=r0; r<r1; r++){
        int info = rowinfo[b*Tt + r];
        int s = info >> 16, e = info & 0xffff;
        float a0=0.f,a1=0.f,a2=0.f;
        int cnt = 0;
        for (int t=s;t<e;t++){
            if (labs[t] != 0){
                cnt++;
                const float* hp = hidden + ((size_t)(b*Tt)+t)*Hh;
                a0 += hp[tid]; a1 += hp[tid+256]; a2 += hp[tid+512];
            }
        }
        float inv = 1.0f / (float)cnt;
        float* op = pooled + ((size_t)(d*Tt)+r)*Hh;
        op[tid] = a0*inv; op[tid+256] = a1*inv; op[tid+512] = a2*inv;
    }
}

// ---------------- row log-softmax over sc ---------------------------------------
__global__ void __launch_bounds__(256) lsm_kernel(
    const float* __restrict__ sc, const int* __restrict__ nvout, float* __restrict__ out)
{
    int row = blockIdx.x*8 + (threadIdx.x >> 5);
    int lane = threadIdx.x & 31;
    int nv = nvout[row >> 9];
    float* op = out + (size_t)row*Nn;
    if ((row & 511) >= nv){
        const float CNEG = -7.6246189861593985f;   // -log(2048)
        float4 c4 = make_float4(CNEG,CNEG,CNEG,CNEG);
        for (int i=lane;i<Nn/4;i+=32) ((float4*)op)[i] = c4;
        return;
    }
    const float4* ip = (const float4*)(sc + (size_t)row*Nn);
    float4 v[16];
    float m = -3.4e38f;
    #pragma unroll
    for (int i=0;i<16;i++){
        v[i] = ip[lane + i*32];
        m = fmaxf(m, fmaxf(fmaxf(v[i].x,v[i].y), fmaxf(v[i].z,v[i].w)));
    }
    #pragma unroll
    for (int off=16;off;off>>=1) m = fmaxf(m, __shfl_xor_sync(0xffffffffu, m, off));
    float s = 0.f;
    #pragma unroll
    for (int i=0;i<16;i++)
        s += expf(v[i].x-m)+expf(v[i].y-m)+expf(v[i].z-m)+expf(v[i].w-m);
    #pragma unroll
    for (int off=16;off;off>>=1) s += __shfl_xor_sync(0xffffffffu, s, off);
    float corr = m + logf(s);
    #pragma unroll
    for (int i=0;i<16;i++){
        float4 o = v[i];
        o.x-=corr; o.y-=corr; o.z-=corr; o.w-=corr;
        ((float4*)op)[lane + i*32] = o;
    }
}

// ---------------- host -----------------------------------------------------------
extern "C" void kernel_launch(void* const* d_in, const int* in_sizes, int n_in,
                              void* d_out, int out_size)
{
    (void)in_sizes; (void)n_in; (void)out_size;
    const int*   labels = (const int*)  d_in[0];
    const float* hidden = (const float*)d_in[1];
    const float* ent    = (const float*)d_in[2];
    const float* W1     = (const float*)d_in[3];
    const float* b1     = (const float*)d_in[4];
    const float* W2     = (const float*)d_in[5];
    const float* b2     = (const float*)d_in[6];
    const float* Wm     = (const float*)d_in[7];
    const float* Wd     = (const float*)d_in[8];

    float* out0 = (float*)d_out;
    float* s1o  = out0 + (size_t)BT*3;
    float* s2o  = s1o  + (size_t)BT*Nn;

    float *h, *pooled, *pm, *pd, *sc;
    int *pred, *rowinfo, *nvraw, *dest, *nvout, *rowvalid;
    cudaGetSymbolAddress((void**)&h,      g_h);
    cudaGetSymbolAddress((void**)&pooled, g_pooled);
    cudaGetSymbolAddress((void**)&pm,     g_pm);
    cudaGetSymbolAddress((void**)&pd,     g_pd);
    cudaGetSymbolAddress((void**)&sc,     g_sc);
    cudaGetSymbolAddress((void**)&pred,   g_pred);
    cudaGetSymbolAddress((void**)&rowinfo,g_rowinfo);
    cudaGetSymbolAddress((void**)&nvraw,  g_nvraw);
    cudaGetSymbolAddress((void**)&dest,   g_dest);
    cudaGetSymbolAddress((void**)&nvout,  g_nvout);
    cudaGetSymbolAddress((void**)&rowvalid,g_rowvalid);

    cudaFuncSetAttribute((const void*)mma_gemm<EP_BIASRELU,false>, cudaFuncAttributeMaxDynamicSharedMemorySize, SMEMSZ);
    cudaFuncSetAttribute((const void*)mma_gemm<EP_PAD,false>,      cudaFuncAttributeMaxDynamicSharedMemorySize, SMEMSZ);
    cudaFuncSetAttribute((const void*)mma_gemm<EP_PAD,true>,       cudaFuncAttributeMaxDynamicSharedMemorySize, SMEMSZ);
    cudaFuncSetAttribute((const void*)mma_gemm<EP_PLAIN,true>,     cudaFuncAttributeMaxDynamicSharedMemorySize, SMEMSZ);

    // 1) h = relu(x @ W1^T + b1)
    mma_gemm<EP_BIASRELU,false><<<dim3(Hh/128, BT/128), 256, SMEMSZ>>>(
        hidden, W1, h, Hh, Hh, Hh, Hh, Hh, Hh, b1, nullptr);

    // 2) bio logits -> out0 + predicted labels
    logits_kernel<<<BT/8, 256>>>(h, W2, b2, out0, pred);

    // 3) pd = ent @ Wd^T, K-padded to KP cols
    mma_gemm<EP_PAD,false><<<dim3(3, Nn/128), 256, SMEMSZ>>>(
        ent, Wd, pd, Hh, Hh, KP, Hh, Pp, Pp, nullptr, nullptr);

    // 4/5) two pooling passes: gold labels, then predicted
    for (int pass = 0; pass < 2; pass++){
        const int* lsrc = (pass == 0) ? labels : pred;
        float* so = (pass == 0) ? s1o : s2o;

        scan_kernel<<<Bb, 32>>>(lsrc, rowinfo, nvraw, rowvalid);
        combine_kernel<<<1, 1>>>(nvraw, rowvalid, dest, nvout);
        pool_kernel<<<dim3(Bb, 16), 256>>>(lsrc, hidden, rowinfo, nvraw, dest, pooled);

        mma_gemm<EP_PAD,true><<<dim3(3, BT/128), 256, SMEMSZ>>>(
            pooled, Wm, pm, Hh, Hh, KP, Hh, Pp, Pp, nullptr, nvout);

        mma_gemm<EP_PLAIN,true><<<dim3(Nn/128, BT/128), 256, SMEMSZ>>>(
            pm, pd, sc, KP, KP, Nn, KP, Nn, Nn, nullptr, nvout);

        lsm_kernel<<<BT/8, 256>>>(sc, nvout, so);
    }
}